// round 15
// baseline (speedup 1.0000x reference)
#include <cuda_runtime.h>
#include <cstdint>
#include <cstddef>

#define TOK 8192          // 4 * 2048 tokens
#define DM  2048          // d_model
#define HID 8192          // hidden

// ---------------- scratch (device globals) ----------------
__device__ float              g_s[2];
__device__ unsigned long long g_tot[2];                // fixed-point |w| sums (2^38)
__device__ signed char        g_wgv_q [2u * HID * DM];
__device__ signed char        g_wout_q[(size_t)DM * HID];
__device__ signed char        g_xq    [(size_t)TOK * DM];
__device__ float              g_d1[TOK];
__device__ float              g_h2   [(size_t)TOK * HID];
__device__ unsigned           g_amax2[TOK];
__device__ signed char        g_h2q  [(size_t)TOK * HID];
__device__ float              g_d2[TOK];

// ---------------- helpers ----------------
__device__ __forceinline__ unsigned smemU32(const void* p) {
    return (unsigned)__cvta_generic_to_shared(p);
}
__device__ __forceinline__ void ldm_x4(unsigned& r0, unsigned& r1, unsigned& r2, unsigned& r3,
                                       unsigned addr) {
    asm volatile("ldmatrix.sync.aligned.m8n8.x4.shared.b16 {%0,%1,%2,%3}, [%4];"
                 : "=r"(r0), "=r"(r1), "=r"(r2), "=r"(r3) : "r"(addr));
}
__device__ __forceinline__ void ldm_x2(unsigned& r0, unsigned& r1, unsigned addr) {
    asm volatile("ldmatrix.sync.aligned.m8n8.x2.shared.b16 {%0,%1}, [%2];"
                 : "=r"(r0), "=r"(r1) : "r"(addr));
}
__device__ __forceinline__ void mma_s8(int* c, const unsigned* a, const unsigned* b) {
    asm volatile("mma.sync.aligned.m16n8k32.row.col.s32.s8.s8.s32 "
                 "{%0,%1,%2,%3}, {%4,%5,%6,%7}, {%8,%9}, {%0,%1,%2,%3};"
                 : "+r"(c[0]), "+r"(c[1]), "+r"(c[2]), "+r"(c[3])
                 : "r"(a[0]), "r"(a[1]), "r"(a[2]), "r"(a[3]), "r"(b[0]), "r"(b[1]));
}
__device__ __forceinline__ int2 lds64(unsigned addr) {
    int2 v;
    asm volatile("ld.shared.v2.u32 {%0,%1}, [%2];" : "=r"(v.x), "=r"(v.y) : "r"(addr));
    return v;
}
__device__ __forceinline__ void cpa16(unsigned dst, const void* src) {
    asm volatile("cp.async.cg.shared.global [%0], [%1], 16;" :: "r"(dst), "l"(src));
}
__device__ __forceinline__ signed char q8(float h, float sc) {
    float r = rintf(h * sc);
    r = fmaxf(-127.f, fminf(127.f, r));
    return (signed char)r;
}

// ---------------- 0) zero weight-sum accumulators ----------------
__global__ void k_zero() {
    if (threadIdx.x < 2) g_tot[threadIdx.x] = 0ull;
}

// ---------------- 1) RMSNorm + per-token act quant (zeroes g_amax2 row) --------------
__global__ void k_rmsquant(const float4* __restrict__ x, const float4* __restrict__ nw) {
    int row = blockIdx.x, t = threadIdx.x;
    int lane = t & 31, warp = t >> 5;
    if (t == 0) g_amax2[row] = 0u;
    const float4* xr = x + (size_t)row * (DM / 4);
    float4 v0 = xr[t], v1 = xr[t + 256];
    float ss = v0.x * v0.x + v0.y * v0.y + v0.z * v0.z + v0.w * v0.w
             + v1.x * v1.x + v1.y * v1.y + v1.z * v1.z + v1.w * v1.w;

    __shared__ float red[8];
    __shared__ float bval;
    for (int o = 16; o; o >>= 1) ss += __shfl_xor_sync(~0u, ss, o);
    if (lane == 0) red[warp] = ss;
    __syncthreads();
    if (t == 0) {
        float s = 0.f;
        #pragma unroll
        for (int i = 0; i < 8; i++) s += red[i];
        bval = s;
    }
    __syncthreads();
    float rstd = rsqrtf(bval * (1.f / DM) + 1e-5f);

    float4 w0 = nw[t], w1 = nw[t + 256];
    float h[8] = { v0.x * rstd * w0.x, v0.y * rstd * w0.y, v0.z * rstd * w0.z, v0.w * rstd * w0.w,
                   v1.x * rstd * w1.x, v1.y * rstd * w1.y, v1.z * rstd * w1.z, v1.w * rstd * w1.w };
    float am = 0.f;
    #pragma unroll
    for (int i = 0; i < 8; i++) am = fmaxf(am, fabsf(h[i]));
    __syncthreads();
    for (int o = 16; o; o >>= 1) am = fmaxf(am, __shfl_xor_sync(~0u, am, o));
    if (lane == 0) red[warp] = am;
    __syncthreads();
    if (t == 0) {
        float m = 0.f;
        #pragma unroll
        for (int i = 0; i < 8; i++) m = fmaxf(m, red[i]);
        m = fmaxf(m, 1e-5f);
        bval = m;
        g_d1[row] = m * (1.f / 127.f);
    }
    __syncthreads();
    float sc = 127.f / bval;

    char4 c0, c1;
    c0.x = q8(h[0], sc); c0.y = q8(h[1], sc); c0.z = q8(h[2], sc); c0.w = q8(h[3], sc);
    c1.x = q8(h[4], sc); c1.y = q8(h[5], sc); c1.z = q8(h[6], sc); c1.w = q8(h[7], sc);
    char4* dst = (char4*)(g_xq + (size_t)row * DM);
    dst[t] = c0;
    dst[t + 256] = c1;
}

// ---------------- 2) abs-mean via deterministic fixed-point atomics ----------------
__global__ void k_absmean(const float4* __restrict__ wgv, const float4* __restrict__ wout) {
    int sel = blockIdx.x >= 1024;
    const float4* p = sel ? wout : wgv;
    int n4 = sel ? (DM * HID / 4) : (2 * HID * DM / 4);
    int b = blockIdx.x & 1023;
    float acc = 0.f;
    for (int i = b * 256 + threadIdx.x; i < n4; i += 1024 * 256) {
        float4 v = p[i];
        acc += fabsf(v.x) + fabsf(v.y) + fabsf(v.z) + fabsf(v.w);
    }
    __shared__ float sm[8];
    for (int o = 16; o; o >>= 1) acc += __shfl_xor_sync(~0u, acc, o);
    if ((threadIdx.x & 31) == 0) sm[threadIdx.x >> 5] = acc;
    __syncthreads();
    if (threadIdx.x == 0) {
        double t = 0.0;
        #pragma unroll
        for (int i = 0; i < 8; i++) t += (double)sm[i];
        atomicAdd(&g_tot[sel], (unsigned long long)(t * 274877906944.0)); // 2^38
    }
}

// ---------------- 3) ternary weight quantization (scale computed inline) -------------
__global__ void k_wquant(const float4* __restrict__ w, int n4, int sel) {
    __shared__ float ssc;
    if (threadIdx.x == 0) {
        double m = (double)g_tot[sel] * (1.0 / 274877906944.0) / ((double)n4 * 4.0);
        float s = fmaxf((float)m, 1e-5f);
        ssc = 1.0f / s;
        if (blockIdx.x == 0) g_s[sel] = s;
    }
    __syncthreads();
    float inv = ssc;
    char4* q = sel ? (char4*)g_wout_q : (char4*)g_wgv_q;
    for (int i = blockIdx.x * blockDim.x + threadIdx.x; i < n4; i += gridDim.x * blockDim.x) {
        float4 v = w[i];
        char4 c;
        c.x = (signed char)fmaxf(-1.f, fminf(1.f, rintf(v.x * inv)));
        c.y = (signed char)fmaxf(-1.f, fminf(1.f, rintf(v.y * inv)));
        c.z = (signed char)fmaxf(-1.f, fminf(1.f, rintf(v.z * inv)));
        c.w = (signed char)fmaxf(-1.f, fminf(1.f, rintf(v.w * inv)));
        q[i] = c;
    }
}

// ============== fused dual-pipe GEMM, rebalanced tensor 80 : dp4a 48 =================
// 512 threads. Warps 0-7 (tensor): wm=warp&3, wn=warp>>2; warp tile 32 x 40 per set
//   (P1: 2 x4 + 1 x2 ldsm per set, NT=5) / 32 x 80 (P2: 5 x4, NT=10). acc = 80.
// Warps 8-15 (dp4a): 16(ti) x 16(ci), thread tile 8 tok x 6 slots (stride-16 rows,
//   swizzle-safe), x/y-split inner loop (R13). acc = 48.
// smem stage rows: A[0,128) | tB[128,288) | dB[288,384), 128B swizzled rows = 48KB.
#define STAGE 49152
#define SMEM_SZ (1024 + 2 * STAGE)

template <int PHASE>
__global__ __launch_bounds__(512, 1) void k_fused(const float* __restrict__ resid,
                                                  float* __restrict__ dout) {
    constexpr int NSETS = (PHASE == 1) ? 2 : 1;
    constexpr int NT    = (PHASE == 1) ? 5 : 10;   // n8-tiles per warp per set
    constexpr int K  = (PHASE == 1) ? DM : HID;
    constexpr int NK = K / 128;
    const signed char* A = (PHASE == 1) ? g_xq : g_h2q;
    const signed char* B = (PHASE == 1) ? g_wgv_q : g_wout_q;
    const float* dA = (PHASE == 1) ? g_d1 : g_d2;

    extern __shared__ char dsm[];
    __shared__ unsigned s_amax[128];

    const int tid = threadIdx.x, lane = tid & 31, warp = tid >> 5;
    const int mBase = blockIdx.y * 128;
    const int nT = blockIdx.x * ((PHASE == 1) ? 128 : 256);

    unsigned dsmAddr = smemU32(dsm);
    unsigned tiles = (dsmAddr + 1023) & ~1023u;

    // ---- loader: 6 x 16B chunks/thread; 80/48 row map (R9-validated) ----
    const int ch = tid & 7, row0 = tid >> 3;          // row0: 0..63
    const unsigned d0 = (unsigned)(row0 * 128 + ((ch ^ (row0 & 7)) << 4));
    const signed char* src[6];
    #pragma unroll
    for (int j = 0; j < 6; j++) {
        int r = row0 + j * 64;
        const signed char* p;
        if (PHASE == 1) {
            if      (r < 128) p = A + (size_t)(mBase + r) * K;
            else if (r < 208) p = B + (size_t)(nT + (r - 128)) * K;
            else if (r < 288) p = B + (size_t)(HID + nT + (r - 208)) * K;
            else if (r < 336) p = B + (size_t)(nT + 80 + (r - 288)) * K;
            else              p = B + (size_t)(HID + nT + 80 + (r - 336)) * K;
        } else {
            if      (r < 128) p = A + (size_t)(mBase + r) * K;
            else if (r < 288) p = B + (size_t)(nT + (r - 128)) * K;
            else              p = B + (size_t)(nT + 160 + (r - 288)) * K;
        }
        src[j] = p + ch * 16;
    }

    auto load = [&](int kt) {
        unsigned sb = tiles + (kt & 1) * STAGE;
        size_t ko = (size_t)kt * 128;
        #pragma unroll
        for (int j = 0; j < 6; j++) cpa16(sb + d0 + j * 8192, src[j] + ko);
    };

    int acc[80];          // tensor warps: 80 mma acc; dp4a warps: 48 used
    #pragma unroll
    for (int i = 0; i < 80; i++) acc[i] = 0;

    if (PHASE == 1)
        for (int i = tid; i < 128; i += 512) s_amax[i] = 0u;

    // per-branch constants
    const int wm = warp & 3, wn = warp >> 2;          // tensor mapping (warps 0-7)
    const int sub = lane >> 3;
    const int t2 = tid - 256;                         // dp4a mapping (warps 8-15)
    const int ti = t2 >> 4, ci = t2 & 15;
    const int aSw = ti & 7, bSw = ci & 7;
    int dRow[6];
    #pragma unroll
    for (int l = 0; l < 6; l++) {
        if (PHASE == 1) dRow[l] = (l < 3) ? ((ci + 16 * l) * 128)
                                          : ((48 + ci + 16 * (l - 3)) * 128);
        else            dRow[l] = (ci + 16 * l) * 128;
    }

    load(0); asm volatile("cp.async.commit_group;");
    load(1); asm volatile("cp.async.commit_group;");

    #pragma unroll 1
    for (int it = 0; it < NK; ++it) {
        asm volatile("cp.async.wait_group 1;");
        __syncthreads();
        unsigned aB = tiles + (it & 1) * STAGE;
        if (warp < 8) {
            // ---------------- tensor warps: 40/80 cols per warp per set ----------------
            unsigned bB = aB + 16384;                 // tB rows base (row 128)
            #pragma unroll
            for (int kk = 0; kk < 4; ++kk) {
                unsigned a[2][4];
                #pragma unroll
                for (int mt = 0; mt < 2; ++mt) {
                    int r = wm * 32 + mt * 16 + (sub & 1) * 8 + (lane & 7);
                    int c = kk * 2 + (sub >> 1);
                    ldm_x4(a[mt][0], a[mt][1], a[mt][2], a[mt][3],
                           aB + r * 128 + ((c ^ (r & 7)) << 4));
                }
                #pragma unroll
                for (int s = 0; s < NSETS; s++) {
                    unsigned b[NT][2];
                    if (PHASE == 1) {
                        #pragma unroll
                        for (int ld = 0; ld < 2; ld++) {
                            int r = s * 80 + wn * 40 + ld * 16 + (sub >> 1) * 8 + (lane & 7);
                            int c = kk * 2 + (sub & 1);
                            unsigned q0, q1, q2, q3;
                            ldm_x4(q0, q1, q2, q3, bB + r * 128 + ((c ^ (r & 7)) << 4));
                            b[ld * 2][0] = q0;     b[ld * 2][1] = q1;
                            b[ld * 2 + 1][0] = q2; b[ld * 2 + 1][1] = q3;
                        }
                        {   // remainder 8 rows via ldsm.x2 (R9-validated mapping)
                            int r = s * 80 + wn * 40 + 32 + (lane & 7);
                            int c = kk * 2 + ((lane >> 3) & 1);
                            ldm_x2(b[4][0], b[4][1], bB + r * 128 + ((c ^ (r & 7)) << 4));
                        }
                    } else {
                        #pragma unroll
                        for (int ld = 0; ld < 5; ld++) {
                            int r = wn * 80 + ld * 16 + (sub >> 1) * 8 + (lane & 7);
                            int c = kk * 2 + (sub & 1);
                            unsigned q0, q1, q2, q3;
                            ldm_x4(q0, q1, q2, q3, bB + r * 128 + ((c ^ (r & 7)) << 4));
                            b[ld * 2][0] = q0;     b[ld * 2][1] = q1;
                            b[ld * 2 + 1][0] = q2; b[ld * 2 + 1][1] = q3;
                        }
                    }
                    #pragma unroll
                    for (int mt = 0; mt < 2; mt++)
                        #pragma unroll
                        for (int nt = 0; nt < NT; nt++)
                            mma_s8(&acc[(((s * 2 + mt) * NT) + nt) * 4], a[mt], b[nt]);
                }
            }
        } else {
            // ---------------- dp4a warps: 48/96 cols, x/y-split (R13) ----------------
            unsigned dBb = aB + 36864;                // dB rows base (row 288)
            unsigned aBase = aB + ti * 128;
            #pragma unroll 2
            for (int h = 0; h < 16; ++h) {
                int kb = h >> 1, half = (h & 1) << 3;
                unsigned aOff = aBase + (((kb ^ aSw) << 4) + half);
                unsigned co = (((kb ^ bSw) << 4) + half);
                int2 a2[8], b2[6];
                #pragma unroll
                for (int j = 0; j < 8; j++) a2[j] = lds64(aOff + j * 2048);
                #pragma unroll
                for (int l = 0; l < 6; l++) b2[l] = lds64(dBb + dRow[l] + co);
                #pragma unroll
                for (int j = 0; j < 8; j++)
                    #pragma unroll
                    for (int l = 0; l < 6; l++)
                        acc[j * 6 + l] = __dp4a(a2[j].x, b2[l].x, acc[j * 6 + l]);
                #pragma unroll
                for (int j = 0; j < 8; j++)
                    #pragma unroll
                    for (int l = 0; l < 6; l++)
                        acc[j * 6 + l] = __dp4a(a2[j].y, b2[l].y, acc[j * 6 + l]);
            }
        }
        __syncthreads();
        if (it + 2 < NK) load(it + 2);
        asm volatile("cp.async.commit_group;");
    }

    // ---------------- epilogues ----------------
    float sw = g_s[PHASE - 1];
    if (warp < 8) {
        #pragma unroll
        for (int mt = 0; mt < 2; ++mt) {
            #pragma unroll
            for (int rh = 0; rh < 2; ++rh) {
                int rloc = wm * 32 + mt * 16 + rh * 8 + (lane >> 2);
                int grow = mBase + rloc;
                float d = dA[grow] * sw;
                if (PHASE == 1) {
                    float rmax = 0.f;
                    #pragma unroll
                    for (int nt = 0; nt < 5; nt++) {
                        float v0 = acc[((mt * 5) + nt) * 4 + rh * 2] * d;
                        float v1 = acc[((mt * 5) + nt) * 4 + rh * 2 + 1] * d;
                        float gg0 = acc[(((2 + mt) * 5) + nt) * 4 + rh * 2] * d;
                        float gg1 = acc[(((2 + mt) * 5) + nt) * 4 + rh * 2 + 1] * d;
                        float h0 = v0 * (gg0 / (1.f + expf(-gg0)));
                        float h1 = v1 * (gg1 / (1.f + expf(-gg1)));
                        rmax = fmaxf(rmax, fmaxf(fabsf(h0), fabsf(h1)));
                        int gc = nT + wn * 40 + nt * 8 + (lane & 3) * 2;
                        *(float2*)(g_h2 + (size_t)grow * HID + gc) = make_float2(h0, h1);
                    }
                    atomicMax(&s_amax[rloc], __float_as_uint(rmax));
                } else {
                    #pragma unroll
                    for (int nt = 0; nt < 10; nt++) {
                        int gc = nT + wn * 80 + nt * 8 + (lane & 3) * 2;
                        float2 rr = *(const float2*)(resid + (size_t)grow * DM + gc);
                        float2 o = make_float2(rr.x + acc[(mt * 10 + nt) * 4 + rh * 2] * d,
                                               rr.y + acc[(mt * 10 + nt) * 4 + rh * 2 + 1] * d);
                        *(float2*)(dout + (size_t)grow * DM + gc) = o;
                    }
                }
            }
        }
    } else {
        #pragma unroll
        for (int j = 0; j < 8; j++) {
            int tok = ti + 16 * j;
            int grow = mBase + tok;
            float d = dA[grow] * sw;
            if (PHASE == 1) {
                float rmax = 0.f;
                #pragma unroll
                for (int l = 0; l < 3; l++) {
                    float v = acc[j * 6 + l] * d;
                    float g = acc[j * 6 + 3 + l] * d;
                    float h = v * (g / (1.f + expf(-g)));
                    rmax = fmaxf(rmax, fabsf(h));
                    g_h2[(size_t)grow * HID + nT + 80 + ci + 16 * l] = h;
                }
                atomicMax(&s_amax[tok], __float_as_uint(rmax));
            } else {
                #pragma unroll
                for (int l = 0; l < 6; l++) {
                    int gc = nT + 160 + ci + 16 * l;
                    dout[(size_t)grow * DM + gc] =
                        resid[(size_t)grow * DM + gc] + acc[j * 6 + l] * d;
                }
            }
        }
    }
    if (PHASE == 1) {
        __syncthreads();
        for (int i = tid; i < 128; i += 512)
            atomicMax(&g_amax2[mBase + i], s_amax[i]);
    }
}

// ---------------- quantize h2 ----------------
__global__ void k_h2quant() {
    int row = blockIdx.y;
    float am = fmaxf(__uint_as_float(g_amax2[row]), 1e-5f);
    float sc = 127.f / am;
    int i = blockIdx.x * 256 + threadIdx.x;
    float4 v = ((const float4*)(g_h2 + (size_t)row * HID))[i];
    char4 c;
    c.x = q8(v.x, sc); c.y = q8(v.y, sc); c.z = q8(v.z, sc); c.w = q8(v.w, sc);
    ((char4*)(g_h2q + (size_t)row * HID))[i] = c;
    if (i == 0) g_d2[row] = am * (1.f / 127.f);
}

// ---------------- launcher: proper capture fork (R5 pattern) ----------------
extern "C" void kernel_launch(void* const* d_in, const int* in_sizes, int n_in,
                              void* d_out, int out_size) {
    const float* x    = (const float*)d_in[0];
    const float* nw   = (const float*)d_in[1];
    const float* wgv  = (const float*)d_in[2];
    const float* wout = (const float*)d_in[3];
    float* out = (float*)d_out;

    static bool inited = false;
    static cudaStream_t sB;
    static cudaEvent_t evS, evR, evA, evW;
    if (!inited) {
        cudaStreamCreateWithFlags(&sB, cudaStreamNonBlocking);
        cudaEventCreateWithFlags(&evS, cudaEventDisableTiming);
        cudaEventCreateWithFlags(&evR, cudaEventDisableTiming);
        cudaEventCreateWithFlags(&evA, cudaEventDisableTiming);
        cudaEventCreateWithFlags(&evW, cudaEventDisableTiming);
        cudaFuncSetAttribute(k_fused<1>, cudaFuncAttributeMaxDynamicSharedMemorySize, SMEM_SZ);
        cudaFuncSetAttribute(k_fused<2>, cudaFuncAttributeMaxDynamicSharedMemorySize, SMEM_SZ);
        inited = true;
    }
    const cudaStream_t s0 = 0;

    k_zero<<<1, 32, 0, s0>>>();                       // origin of capture
    cudaEventRecord(evS, s0);
    cudaStreamWaitEvent(sB, evS, 0);                  // fork sB INTO the capture

    k_rmsquant<<<TOK, 256, 0, sB>>>((const float4*)x, (const float4*)nw);   // side
    cudaEventRecord(evR, sB);

    k_absmean<<<2048, 256, 0, s0>>>((const float4*)wgv, (const float4*)wout);
    cudaEventRecord(evA, s0);
    k_wquant<<<4096, 256, 0, s0>>>((const float4*)wgv, 2 * HID * DM / 4, 0);

    cudaStreamWaitEvent(s0, evR, 0);
    k_fused<1><<<dim3(HID / 128, TOK / 128), 512, SMEM_SZ, s0>>>(nullptr, nullptr);

    cudaStreamWaitEvent(sB, evA, 0);
    k_wquant<<<2048, 256, 0, sB>>>((const float4*)wout, DM * HID / 4, 1);   // hides under fused1
    cudaEventRecord(evW, sB);

    k_h2quant<<<dim3(8, TOK), 256, 0, s0>>>();
    cudaStreamWaitEvent(s0, evW, 0);
    k_fused<2><<<dim3(DM / 256, TOK / 128), 512, SMEM_SZ, s0>>>(x, out);
}

// round 16
// speedup vs baseline: 1.0897x; 1.0897x over previous
#include <cuda_runtime.h>
#include <cstdint>
#include <cstddef>

#define TOK 8192          // 4 * 2048 tokens
#define DM  2048          // d_model
#define HID 8192          // hidden

// ---------------- scratch (device globals) ----------------
__device__ float              g_s[2];
__device__ unsigned long long g_tot[2];                // fixed-point |w| sums (2^38)
__device__ signed char        g_wgv_q [2u * HID * DM];
__device__ signed char        g_wout_q[(size_t)DM * HID];
__device__ signed char        g_xq    [(size_t)TOK * DM];
__device__ float              g_d1[TOK];
__device__ float              g_h2   [(size_t)TOK * HID];
__device__ unsigned           g_amax2[TOK];
__device__ signed char        g_h2q  [(size_t)TOK * HID];
__device__ float              g_d2[TOK];

// ---------------- helpers ----------------
__device__ __forceinline__ unsigned smemU32(const void* p) {
    return (unsigned)__cvta_generic_to_shared(p);
}
__device__ __forceinline__ void ldm_x4(unsigned& r0, unsigned& r1, unsigned& r2, unsigned& r3,
                                       unsigned addr) {
    asm volatile("ldmatrix.sync.aligned.m8n8.x4.shared.b16 {%0,%1,%2,%3}, [%4];"
                 : "=r"(r0), "=r"(r1), "=r"(r2), "=r"(r3) : "r"(addr));
}
__device__ __forceinline__ void mma_s8(int* c, const unsigned* a, const unsigned* b) {
    asm volatile("mma.sync.aligned.m16n8k32.row.col.s32.s8.s8.s32 "
                 "{%0,%1,%2,%3}, {%4,%5,%6,%7}, {%8,%9}, {%0,%1,%2,%3};"
                 : "+r"(c[0]), "+r"(c[1]), "+r"(c[2]), "+r"(c[3])
                 : "r"(a[0]), "r"(a[1]), "r"(a[2]), "r"(a[3]), "r"(b[0]), "r"(b[1]));
}
__device__ __forceinline__ int2 lds64(unsigned addr) {
    int2 v;
    asm volatile("ld.shared.v2.u32 {%0,%1}, [%2];" : "=r"(v.x), "=r"(v.y) : "r"(addr));
    return v;
}
__device__ __forceinline__ void cpa16(unsigned dst, const void* src) {
    asm volatile("cp.async.cg.shared.global [%0], [%1], 16;" :: "r"(dst), "l"(src));
}
__device__ __forceinline__ signed char q8(float h, float sc) {
    float r = rintf(h * sc);
    r = fmaxf(-127.f, fminf(127.f, r));
    return (signed char)r;
}

// ---------------- 0) zero weight-sum accumulators ----------------
__global__ void k_zero() {
    if (threadIdx.x < 2) g_tot[threadIdx.x] = 0ull;
}

// ---------------- 1) RMSNorm + per-token act quant (zeroes g_amax2 row) --------------
__global__ void k_rmsquant(const float4* __restrict__ x, const float4* __restrict__ nw) {
    int row = blockIdx.x, t = threadIdx.x;
    int lane = t & 31, warp = t >> 5;
    if (t == 0) g_amax2[row] = 0u;
    const float4* xr = x + (size_t)row * (DM / 4);
    float4 v0 = xr[t], v1 = xr[t + 256];
    float ss = v0.x * v0.x + v0.y * v0.y + v0.z * v0.z + v0.w * v0.w
             + v1.x * v1.x + v1.y * v1.y + v1.z * v1.z + v1.w * v1.w;

    __shared__ float red[8];
    __shared__ float bval;
    for (int o = 16; o; o >>= 1) ss += __shfl_xor_sync(~0u, ss, o);
    if (lane == 0) red[warp] = ss;
    __syncthreads();
    if (t == 0) {
        float s = 0.f;
        #pragma unroll
        for (int i = 0; i < 8; i++) s += red[i];
        bval = s;
    }
    __syncthreads();
    float rstd = rsqrtf(bval * (1.f / DM) + 1e-5f);

    float4 w0 = nw[t], w1 = nw[t + 256];
    float h[8] = { v0.x * rstd * w0.x, v0.y * rstd * w0.y, v0.z * rstd * w0.z, v0.w * rstd * w0.w,
                   v1.x * rstd * w1.x, v1.y * rstd * w1.y, v1.z * rstd * w1.z, v1.w * rstd * w1.w };
    float am = 0.f;
    #pragma unroll
    for (int i = 0; i < 8; i++) am = fmaxf(am, fabsf(h[i]));
    __syncthreads();
    for (int o = 16; o; o >>= 1) am = fmaxf(am, __shfl_xor_sync(~0u, am, o));
    if (lane == 0) red[warp] = am;
    __syncthreads();
    if (t == 0) {
        float m = 0.f;
        #pragma unroll
        for (int i = 0; i < 8; i++) m = fmaxf(m, red[i]);
        m = fmaxf(m, 1e-5f);
        bval = m;
        g_d1[row] = m * (1.f / 127.f);
    }
    __syncthreads();
    float sc = 127.f / bval;

    char4 c0, c1;
    c0.x = q8(h[0], sc); c0.y = q8(h[1], sc); c0.z = q8(h[2], sc); c0.w = q8(h[3], sc);
    c1.x = q8(h[4], sc); c1.y = q8(h[5], sc); c1.z = q8(h[6], sc); c1.w = q8(h[7], sc);
    char4* dst = (char4*)(g_xq + (size_t)row * DM);
    dst[t] = c0;
    dst[t + 256] = c1;
}

// ---------------- 2) abs-mean via deterministic fixed-point atomics ----------------
__global__ void k_absmean(const float4* __restrict__ wgv, const float4* __restrict__ wout) {
    int sel = blockIdx.x >= 1024;
    const float4* p = sel ? wout : wgv;
    int n4 = sel ? (DM * HID / 4) : (2 * HID * DM / 4);
    int b = blockIdx.x & 1023;
    float acc = 0.f;
    for (int i = b * 256 + threadIdx.x; i < n4; i += 1024 * 256) {
        float4 v = p[i];
        acc += fabsf(v.x) + fabsf(v.y) + fabsf(v.z) + fabsf(v.w);
    }
    __shared__ float sm[8];
    for (int o = 16; o; o >>= 1) acc += __shfl_xor_sync(~0u, acc, o);
    if ((threadIdx.x & 31) == 0) sm[threadIdx.x >> 5] = acc;
    __syncthreads();
    if (threadIdx.x == 0) {
        double t = 0.0;
        #pragma unroll
        for (int i = 0; i < 8; i++) t += (double)sm[i];
        atomicAdd(&g_tot[sel], (unsigned long long)(t * 274877906944.0)); // 2^38
    }
}

// ---------------- 3) ternary weight quantization (scale computed inline) -------------
__global__ void k_wquant(const float4* __restrict__ w, int n4, int sel) {
    __shared__ float ssc;
    if (threadIdx.x == 0) {
        double m = (double)g_tot[sel] * (1.0 / 274877906944.0) / ((double)n4 * 4.0);
        float s = fmaxf((float)m, 1e-5f);
        ssc = 1.0f / s;
        if (blockIdx.x == 0) g_s[sel] = s;
    }
    __syncthreads();
    float inv = ssc;
    char4* q = sel ? (char4*)g_wout_q : (char4*)g_wgv_q;
    for (int i = blockIdx.x * blockDim.x + threadIdx.x; i < n4; i += gridDim.x * blockDim.x) {
        float4 v = w[i];
        char4 c;
        c.x = (signed char)fmaxf(-1.f, fminf(1.f, rintf(v.x * inv)));
        c.y = (signed char)fmaxf(-1.f, fminf(1.f, rintf(v.y * inv)));
        c.z = (signed char)fmaxf(-1.f, fminf(1.f, rintf(v.z * inv)));
        c.w = (signed char)fmaxf(-1.f, fminf(1.f, rintf(v.w * inv)));
        q[i] = c;
    }
}

// ============== fused dual-pipe GEMM (R13: 64:64, x/y-split dp4a) ===================
// 512 threads. Warps 0-7: mma.sync on cols [n0, n0+64) (+gate pair for P1).
// Warps 8-15: dp4a on cols [n0+64, n0+128) (P1, + gates) / [n0+128, n0+256) (P2).
#define STAGE 49152
#define SMEM_SZ (1024 + 2 * STAGE)

template <int PHASE>
__global__ __launch_bounds__(512, 1) void k_fused(const float* __restrict__ resid,
                                                  float* __restrict__ dout, int mOff) {
    constexpr int NSETS = (PHASE == 1) ? 2 : 1;
    constexpr int NTP   = (PHASE == 1) ? 2 : 4;
    constexpr int K  = (PHASE == 1) ? DM : HID;
    constexpr int NK = K / 128;
    const signed char* A = (PHASE == 1) ? g_xq : g_h2q;
    const signed char* B = (PHASE == 1) ? g_wgv_q : g_wout_q;
    const float* dA = (PHASE == 1) ? g_d1 : g_d2;

    extern __shared__ char dsm[];
    __shared__ unsigned s_amax[128];

    const int tid = threadIdx.x, lane = tid & 31, warp = tid >> 5;
    const int mBase = mOff + blockIdx.y * 128;
    const int nT = blockIdx.x * ((PHASE == 1) ? 128 : 256);

    unsigned dsmAddr = smemU32(dsm);
    unsigned tiles = (dsmAddr + 1023) & ~1023u;

    const int ch = tid & 7, row0 = tid >> 3;          // row0: 0..63
    const unsigned d0 = (unsigned)(row0 * 128 + ((ch ^ (row0 & 7)) << 4));
    const signed char* pA  = A + (size_t)(mBase + row0) * K + ch * 16;
    const signed char *pTv, *pTg, *pDv, *pDg;
    if (PHASE == 1) {
        pTv = B + (size_t)(nT + row0) * K + ch * 16;
        pTg = B + (size_t)(HID + nT + row0) * K + ch * 16;
        pDv = B + (size_t)(nT + 64 + row0) * K + ch * 16;
        pDg = B + (size_t)(HID + nT + 64 + row0) * K + ch * 16;
    } else {
        pTv = B + (size_t)(nT + row0) * K + ch * 16;
        pTg = B + (size_t)(nT + 64 + row0) * K + ch * 16;
        pDv = B + (size_t)(nT + 128 + row0) * K + ch * 16;
        pDg = B + (size_t)(nT + 192 + row0) * K + ch * 16;
    }

    auto load = [&](int kt) {
        unsigned sb = tiles + (kt & 1) * STAGE;
        size_t ko = (size_t)kt * 128;
        cpa16(sb + d0,                pA  + ko);
        cpa16(sb + d0 + 8192,         pA  + ko + (size_t)64 * K);
        cpa16(sb + 16384 + d0,        pTv + ko);
        cpa16(sb + 16384 + d0 + 8192, pTg + ko);
        cpa16(sb + 32768 + d0,        pDv + ko);
        cpa16(sb + 32768 + d0 + 8192, pDg + ko);
    };

    int acc[64];
    #pragma unroll
    for (int i = 0; i < 64; i++) acc[i] = 0;

    if (PHASE == 1)
        for (int i = tid; i < 128; i += 512) s_amax[i] = 0u;

    const int wm = warp & 3, wn = warp >> 2;          // tensor mapping (warps 0-7)
    const int sub = lane >> 3;
    const int t2 = tid - 256;                         // dp4a mapping (warps 8-15)
    const int ti = t2 >> 4, ci = t2 & 15;
    const int aSw = ti & 7, bSw = ci & 7;

    load(0); asm volatile("cp.async.commit_group;");
    load(1); asm volatile("cp.async.commit_group;");

    #pragma unroll 1
    for (int it = 0; it < NK; ++it) {
        asm volatile("cp.async.wait_group 1;");
        __syncthreads();
        unsigned aB = tiles + (it & 1) * STAGE;
        if (warp < 8) {
            unsigned bB = aB + 16384;
            #pragma unroll
            for (int kk = 0; kk < 4; ++kk) {
                unsigned a[2][4];
                #pragma unroll
                for (int mt = 0; mt < 2; ++mt) {
                    int r = wm * 32 + mt * 16 + (sub & 1) * 8 + (lane & 7);
                    int c = kk * 2 + (sub >> 1);
                    ldm_x4(a[mt][0], a[mt][1], a[mt][2], a[mt][3],
                           aB + r * 128 + ((c ^ (r & 7)) << 4));
                }
                unsigned b[NSETS][NTP * 2][2];
                #pragma unroll
                for (int s = 0; s < NSETS; s++)
                    #pragma unroll
                    for (int ntp = 0; ntp < NTP; ntp++) {
                        int r = s * 64 + wn * (NTP * 16) + ntp * 16 + (sub >> 1) * 8 + (lane & 7);
                        int c = kk * 2 + (sub & 1);
                        unsigned q0, q1, q2, q3;
                        ldm_x4(q0, q1, q2, q3, bB + r * 128 + ((c ^ (r & 7)) << 4));
                        b[s][ntp * 2][0] = q0;     b[s][ntp * 2][1] = q1;
                        b[s][ntp * 2 + 1][0] = q2; b[s][ntp * 2 + 1][1] = q3;
                    }
                #pragma unroll
                for (int s = 0; s < NSETS; s++)
                    #pragma unroll
                    for (int mt = 0; mt < 2; mt++)
                        #pragma unroll
                        for (int nt = 0; nt < NTP * 2; nt++)
                            mma_s8(&acc[(((s * 2 + mt) * (NTP * 2)) + nt) * 4], a[mt], b[s][nt]);
            }
        } else {
            unsigned bB = aB + 32768;
            unsigned aBase = aB + ti * 128;
            unsigned bBase = bB + ci * 128;
            #pragma unroll 2
            for (int h = 0; h < 16; ++h) {
                int kb = h >> 1, half = (h & 1) << 3;
                unsigned aOff = aBase + (((kb ^ aSw) << 4) + half);
                unsigned bOff = bBase + (((kb ^ bSw) << 4) + half);
                int2 a2[8], b2[8];
                #pragma unroll
                for (int j = 0; j < 8; j++) a2[j] = lds64(aOff + j * 2048);
                #pragma unroll
                for (int l = 0; l < 8; l++) b2[l] = lds64(bOff + l * 2048);
                #pragma unroll
                for (int j = 0; j < 8; j++)
                    #pragma unroll
                    for (int l = 0; l < 8; l++)
                        acc[j * 8 + l] = __dp4a(a2[j].x, b2[l].x, acc[j * 8 + l]);
                #pragma unroll
                for (int j = 0; j < 8; j++)
                    #pragma unroll
                    for (int l = 0; l < 8; l++)
                        acc[j * 8 + l] = __dp4a(a2[j].y, b2[l].y, acc[j * 8 + l]);
            }
        }
        __syncthreads();
        if (it + 2 < NK) load(it + 2);
        asm volatile("cp.async.commit_group;");
    }

    // ---------------- epilogues (R13 verbatim) ----------------
    float sw = g_s[PHASE - 1];
    if (warp < 8) {
        #pragma unroll
        for (int mt = 0; mt < 2; ++mt) {
            #pragma unroll
            for (int rh = 0; rh < 2; ++rh) {
                int rloc = wm * 32 + mt * 16 + rh * 8 + (lane >> 2);
                int grow = mBase + rloc;
                float d = dA[grow] * sw;
                if (PHASE == 1) {
                    float rmax = 0.f;
                    #pragma unroll
                    for (int nt = 0; nt < 4; nt++) {
                        float v0 = acc[((mt * 4) + nt) * 4 + rh * 2] * d;
                        float v1 = acc[((mt * 4) + nt) * 4 + rh * 2 + 1] * d;
                        float gg0 = acc[(((2 + mt) * 4) + nt) * 4 + rh * 2] * d;
                        float gg1 = acc[(((2 + mt) * 4) + nt) * 4 + rh * 2 + 1] * d;
                        float h0 = v0 * (gg0 / (1.f + expf(-gg0)));
                        float h1 = v1 * (gg1 / (1.f + expf(-gg1)));
                        rmax = fmaxf(rmax, fmaxf(fabsf(h0), fabsf(h1)));
                        int gc = nT + wn * 32 + nt * 8 + (lane & 3) * 2;
                        *(float2*)(g_h2 + (size_t)grow * HID + gc) = make_float2(h0, h1);
                    }
                    atomicMax(&s_amax[rloc], __float_as_uint(rmax));
                } else {
                    #pragma unroll
                    for (int nt = 0; nt < 8; nt++) {
                        int gc = nT + wn * 64 + nt * 8 + (lane & 3) * 2;
                        float2 rr = *(const float2*)(resid + (size_t)grow * DM + gc);
                        float2 o = make_float2(rr.x + acc[(mt * 8 + nt) * 4 + rh * 2] * d,
                                               rr.y + acc[(mt * 8 + nt) * 4 + rh * 2 + 1] * d);
                        *(float2*)(dout + (size_t)grow * DM + gc) = o;
                    }
                }
            }
        }
    } else {
        #pragma unroll
        for (int j = 0; j < 8; j++) {
            int tok = ti + 16 * j;
            int grow = mBase + tok;
            float d = dA[grow] * sw;
            if (PHASE == 1) {
                float rmax = 0.f;
                #pragma unroll
                for (int l = 0; l < 4; l++) {
                    float v = acc[j * 8 + l] * d;
                    float g = acc[j * 8 + l + 4] * d;
                    float h = v * (g / (1.f + expf(-g)));
                    rmax = fmaxf(rmax, fabsf(h));
                    g_h2[(size_t)grow * HID + nT + 64 + ci + 16 * l] = h;
                }
                atomicMax(&s_amax[tok], __float_as_uint(rmax));
            } else {
                #pragma unroll
                for (int l = 0; l < 8; l++) {
                    int gc = nT + 128 + ci + 16 * l;
                    dout[(size_t)grow * DM + gc] =
                        resid[(size_t)grow * DM + gc] + acc[j * 8 + l] * d;
                }
            }
        }
    }
    if (PHASE == 1) {
        __syncthreads();
        for (int i = tid; i < 128; i += 512)
            atomicMax(&g_amax2[mBase + i], s_amax[i]);
    }
}

// ---------------- quantize h2 (row-chunked) ----------------
__global__ void k_h2quant(int rowOff) {
    int row = rowOff + blockIdx.y;
    float am = fmaxf(__uint_as_float(g_amax2[row]), 1e-5f);
    float sc = 127.f / am;
    int i = blockIdx.x * 256 + threadIdx.x;
    float4 v = ((const float4*)(g_h2 + (size_t)row * HID))[i];
    char4 c;
    c.x = q8(v.x, sc); c.y = q8(v.y, sc); c.z = q8(v.z, sc); c.w = q8(v.w, sc);
    ((char4*)(g_h2q + (size_t)row * HID))[i] = c;
    if (i == 0) g_d2[row] = am * (1.f / 127.f);
}

// ---------------- launcher: forked capture + tail pipeline ----------------
extern "C" void kernel_launch(void* const* d_in, const int* in_sizes, int n_in,
                              void* d_out, int out_size) {
    const float* x    = (const float*)d_in[0];
    const float* nw   = (const float*)d_in[1];
    const float* wgv  = (const float*)d_in[2];
    const float* wout = (const float*)d_in[3];
    float* out = (float*)d_out;

    static bool inited = false;
    static cudaStream_t sB;
    static cudaEvent_t evS, evR, evA, evW, evF1, evH1;
    if (!inited) {
        cudaStreamCreateWithFlags(&sB, cudaStreamNonBlocking);
        cudaEventCreateWithFlags(&evS,  cudaEventDisableTiming);
        cudaEventCreateWithFlags(&evR,  cudaEventDisableTiming);
        cudaEventCreateWithFlags(&evA,  cudaEventDisableTiming);
        cudaEventCreateWithFlags(&evW,  cudaEventDisableTiming);
        cudaEventCreateWithFlags(&evF1, cudaEventDisableTiming);
        cudaEventCreateWithFlags(&evH1, cudaEventDisableTiming);
        cudaFuncSetAttribute(k_fused<1>, cudaFuncAttributeMaxDynamicSharedMemorySize, SMEM_SZ);
        cudaFuncSetAttribute(k_fused<2>, cudaFuncAttributeMaxDynamicSharedMemorySize, SMEM_SZ);
        inited = true;
    }
    const cudaStream_t s0 = 0;
    const int HTOK = TOK / 2;

    k_zero<<<1, 32, 0, s0>>>();                       // origin of capture
    cudaEventRecord(evS, s0);
    cudaStreamWaitEvent(sB, evS, 0);                  // fork sB into capture

    k_rmsquant<<<TOK, 256, 0, sB>>>((const float4*)x, (const float4*)nw);
    cudaEventRecord(evR, sB);

    k_absmean<<<2048, 256, 0, s0>>>((const float4*)wgv, (const float4*)wout);
    cudaEventRecord(evA, s0);
    k_wquant<<<4096, 256, 0, s0>>>((const float4*)wgv, 2 * HID * DM / 4, 0);

    cudaStreamWaitEvent(s0, evR, 0);
    k_fused<1><<<dim3(HID / 128, TOK / 128), 512, SMEM_SZ, s0>>>(nullptr, nullptr, 0);
    cudaEventRecord(evF1, s0);

    cudaStreamWaitEvent(sB, evA, 0);
    k_wquant<<<2048, 256, 0, sB>>>((const float4*)wout, DM * HID / 4, 1);   // hides under fused1
    cudaEventRecord(evW, sB);

    // tail pipeline: h2quant c0 -> fused2 c0 (while h2quant c1 runs on sB) -> fused2 c1
    k_h2quant<<<dim3(8, HTOK), 256, 0, s0>>>(0);

    cudaStreamWaitEvent(sB, evF1, 0);
    k_h2quant<<<dim3(8, HTOK), 256, 0, sB>>>(HTOK);   // concurrent with fused2 c0
    cudaEventRecord(evH1, sB);

    cudaStreamWaitEvent(s0, evW, 0);
    k_fused<2><<<dim3(DM / 256, HTOK / 128), 512, SMEM_SZ, s0>>>(x, out, 0);
    cudaStreamWaitEvent(s0, evH1, 0);
    k_fused<2><<<dim3(DM / 256, HTOK / 128), 512, SMEM_SZ, s0>>>(x, out, HTOK);
}

// round 17
// speedup vs baseline: 1.0926x; 1.0027x over previous
#include <cuda_runtime.h>
#include <cstdint>
#include <cstddef>

#define TOK 8192          // 4 * 2048 tokens
#define DM  2048          // d_model
#define HID 8192          // hidden

// ---------------- scratch (device globals) ----------------
__device__ float              g_s[2];
__device__ unsigned long long g_tot[2];                // fixed-point |w| sums (2^38)
__device__ signed char        g_wgv_q [2u * HID * DM];
__device__ signed char        g_wout_q[(size_t)DM * HID];
__device__ signed char        g_xq    [(size_t)TOK * DM];
__device__ float              g_d1[TOK];
__device__ float              g_h2   [(size_t)TOK * HID];
__device__ unsigned           g_amax2[TOK];
__device__ signed char        g_h2q  [(size_t)TOK * HID];
__device__ float              g_d2[TOK];

// ---------------- helpers ----------------
__device__ __forceinline__ unsigned smemU32(const void* p) {
    return (unsigned)__cvta_generic_to_shared(p);
}
__device__ __forceinline__ void ldm_x4(unsigned& r0, unsigned& r1, unsigned& r2, unsigned& r3,
                                       unsigned addr) {
    asm volatile("ldmatrix.sync.aligned.m8n8.x4.shared.b16 {%0,%1,%2,%3}, [%4];"
                 : "=r"(r0), "=r"(r1), "=r"(r2), "=r"(r3) : "r"(addr));
}
__device__ __forceinline__ void mma_s8(int* c, const unsigned* a, const unsigned* b) {
    asm volatile("mma.sync.aligned.m16n8k32.row.col.s32.s8.s8.s32 "
                 "{%0,%1,%2,%3}, {%4,%5,%6,%7}, {%8,%9}, {%0,%1,%2,%3};"
                 : "+r"(c[0]), "+r"(c[1]), "+r"(c[2]), "+r"(c[3])
                 : "r"(a[0]), "r"(a[1]), "r"(a[2]), "r"(a[3]), "r"(b[0]), "r"(b[1]));
}
__device__ __forceinline__ int2 lds64(unsigned addr) {
    int2 v;
    asm volatile("ld.shared.v2.u32 {%0,%1}, [%2];" : "=r"(v.x), "=r"(v.y) : "r"(addr));
    return v;
}
__device__ __forceinline__ void cpa16(unsigned dst, const void* src) {
    asm volatile("cp.async.cg.shared.global [%0], [%1], 16;" :: "r"(dst), "l"(src));
}
__device__ __forceinline__ signed char q8(float h, float sc) {
    float r = rintf(h * sc);
    r = fmaxf(-127.f, fminf(127.f, r));
    return (signed char)r;
}

// ---------------- 0) zero weight-sum accumulators ----------------
__global__ void k_zero() {
    if (threadIdx.x < 2) g_tot[threadIdx.x] = 0ull;
}

// ---------------- 1) RMSNorm + per-token act quant (zeroes g_amax2 row) --------------
__global__ void k_rmsquant(const float4* __restrict__ x, const float4* __restrict__ nw) {
    int row = blockIdx.x, t = threadIdx.x;
    int lane = t & 31, warp = t >> 5;
    if (t == 0) g_amax2[row] = 0u;
    const float4* xr = x + (size_t)row * (DM / 4);
    float4 v0 = xr[t], v1 = xr[t + 256];
    float ss = v0.x * v0.x + v0.y * v0.y + v0.z * v0.z + v0.w * v0.w
             + v1.x * v1.x + v1.y * v1.y + v1.z * v1.z + v1.w * v1.w;

    __shared__ float red[8];
    __shared__ float bval;
    for (int o = 16; o; o >>= 1) ss += __shfl_xor_sync(~0u, ss, o);
    if (lane == 0) red[warp] = ss;
    __syncthreads();
    if (t == 0) {
        float s = 0.f;
        #pragma unroll
        for (int i = 0; i < 8; i++) s += red[i];
        bval = s;
    }
    __syncthreads();
    float rstd = rsqrtf(bval * (1.f / DM) + 1e-5f);

    float4 w0 = nw[t], w1 = nw[t + 256];
    float h[8] = { v0.x * rstd * w0.x, v0.y * rstd * w0.y, v0.z * rstd * w0.z, v0.w * rstd * w0.w,
                   v1.x * rstd * w1.x, v1.y * rstd * w1.y, v1.z * rstd * w1.z, v1.w * rstd * w1.w };
    float am = 0.f;
    #pragma unroll
    for (int i = 0; i < 8; i++) am = fmaxf(am, fabsf(h[i]));
    __syncthreads();
    for (int o = 16; o; o >>= 1) am = fmaxf(am, __shfl_xor_sync(~0u, am, o));
    if (lane == 0) red[warp] = am;
    __syncthreads();
    if (t == 0) {
        float m = 0.f;
        #pragma unroll
        for (int i = 0; i < 8; i++) m = fmaxf(m, red[i]);
        m = fmaxf(m, 1e-5f);
        bval = m;
        g_d1[row] = m * (1.f / 127.f);
    }
    __syncthreads();
    float sc = 127.f / bval;

    char4 c0, c1;
    c0.x = q8(h[0], sc); c0.y = q8(h[1], sc); c0.z = q8(h[2], sc); c0.w = q8(h[3], sc);
    c1.x = q8(h[4], sc); c1.y = q8(h[5], sc); c1.z = q8(h[6], sc); c1.w = q8(h[7], sc);
    char4* dst = (char4*)(g_xq + (size_t)row * DM);
    dst[t] = c0;
    dst[t + 256] = c1;
}

// ---------------- 2) abs-mean (per tensor) via deterministic fixed-point atomics ------
__global__ void k_absmean(const float4* __restrict__ p, int n4, int sel) {
    int b = blockIdx.x;
    float acc = 0.f;
    for (int i = b * 256 + threadIdx.x; i < n4; i += 1024 * 256) {
        float4 v = p[i];
        acc += fabsf(v.x) + fabsf(v.y) + fabsf(v.z) + fabsf(v.w);
    }
    __shared__ float sm[8];
    for (int o = 16; o; o >>= 1) acc += __shfl_xor_sync(~0u, acc, o);
    if ((threadIdx.x & 31) == 0) sm[threadIdx.x >> 5] = acc;
    __syncthreads();
    if (threadIdx.x == 0) {
        double t = 0.0;
        #pragma unroll
        for (int i = 0; i < 8; i++) t += (double)sm[i];
        atomicAdd(&g_tot[sel], (unsigned long long)(t * 274877906944.0)); // 2^38
    }
}

// ---------------- 3) ternary weight quantization (scale computed inline) -------------
__global__ void k_wquant(const float4* __restrict__ w, int n4, int sel) {
    __shared__ float ssc;
    if (threadIdx.x == 0) {
        double m = (double)g_tot[sel] * (1.0 / 274877906944.0) / ((double)n4 * 4.0);
        float s = fmaxf((float)m, 1e-5f);
        ssc = 1.0f / s;
        if (blockIdx.x == 0) g_s[sel] = s;
    }
    __syncthreads();
    float inv = ssc;
    char4* q = sel ? (char4*)g_wout_q : (char4*)g_wgv_q;
    for (int i = blockIdx.x * blockDim.x + threadIdx.x; i < n4; i += gridDim.x * blockDim.x) {
        float4 v = w[i];
        char4 c;
        c.x = (signed char)fmaxf(-1.f, fminf(1.f, rintf(v.x * inv)));
        c.y = (signed char)fmaxf(-1.f, fminf(1.f, rintf(v.y * inv)));
        c.z = (signed char)fmaxf(-1.f, fminf(1.f, rintf(v.z * inv)));
        c.w = (signed char)fmaxf(-1.f, fminf(1.f, rintf(v.w * inv)));
        q[i] = c;
    }
}

// ============== fused dual-pipe GEMM (R13: 64:64, x/y-split dp4a) ===================
// 512 threads. Warps 0-7: mma.sync on cols [n0, n0+64) (+gate pair for P1).
// Warps 8-15: dp4a on cols [n0+64, n0+128) (P1, + gates) / [n0+128, n0+256) (P2).
#define STAGE 49152
#define SMEM_SZ (1024 + 2 * STAGE)

template <int PHASE>
__global__ __launch_bounds__(512, 1) void k_fused(const float* __restrict__ resid,
                                                  float* __restrict__ dout, int mOff) {
    constexpr int NSETS = (PHASE == 1) ? 2 : 1;
    constexpr int NTP   = (PHASE == 1) ? 2 : 4;
    constexpr int K  = (PHASE == 1) ? DM : HID;
    constexpr int NK = K / 128;
    const signed char* A = (PHASE == 1) ? g_xq : g_h2q;
    const signed char* B = (PHASE == 1) ? g_wgv_q : g_wout_q;
    const float* dA = (PHASE == 1) ? g_d1 : g_d2;

    extern __shared__ char dsm[];
    __shared__ unsigned s_amax[128];

    const int tid = threadIdx.x, lane = tid & 31, warp = tid >> 5;
    const int mBase = mOff + blockIdx.y * 128;
    const int nT = blockIdx.x * ((PHASE == 1) ? 128 : 256);

    unsigned dsmAddr = smemU32(dsm);
    unsigned tiles = (dsmAddr + 1023) & ~1023u;

    const int ch = tid & 7, row0 = tid >> 3;          // row0: 0..63
    const unsigned d0 = (unsigned)(row0 * 128 + ((ch ^ (row0 & 7)) << 4));
    const signed char* pA  = A + (size_t)(mBase + row0) * K + ch * 16;
    const signed char *pTv, *pTg, *pDv, *pDg;
    if (PHASE == 1) {
        pTv = B + (size_t)(nT + row0) * K + ch * 16;
        pTg = B + (size_t)(HID + nT + row0) * K + ch * 16;
        pDv = B + (size_t)(nT + 64 + row0) * K + ch * 16;
        pDg = B + (size_t)(HID + nT + 64 + row0) * K + ch * 16;
    } else {
        pTv = B + (size_t)(nT + row0) * K + ch * 16;
        pTg = B + (size_t)(nT + 64 + row0) * K + ch * 16;
        pDv = B + (size_t)(nT + 128 + row0) * K + ch * 16;
        pDg = B + (size_t)(nT + 192 + row0) * K + ch * 16;
    }

    auto load = [&](int kt) {
        unsigned sb = tiles + (kt & 1) * STAGE;
        size_t ko = (size_t)kt * 128;
        cpa16(sb + d0,                pA  + ko);
        cpa16(sb + d0 + 8192,         pA  + ko + (size_t)64 * K);
        cpa16(sb + 16384 + d0,        pTv + ko);
        cpa16(sb + 16384 + d0 + 8192, pTg + ko);
        cpa16(sb + 32768 + d0,        pDv + ko);
        cpa16(sb + 32768 + d0 + 8192, pDg + ko);
    };

    int acc[64];
    #pragma unroll
    for (int i = 0; i < 64; i++) acc[i] = 0;

    if (PHASE == 1)
        for (int i = tid; i < 128; i += 512) s_amax[i] = 0u;

    const int wm = warp & 3, wn = warp >> 2;          // tensor mapping (warps 0-7)
    const int sub = lane >> 3;
    const int t2 = tid - 256;                         // dp4a mapping (warps 8-15)
    const int ti = t2 >> 4, ci = t2 & 15;
    const int aSw = ti & 7, bSw = ci & 7;

    load(0); asm volatile("cp.async.commit_group;");
    load(1); asm volatile("cp.async.commit_group;");

    #pragma unroll 1
    for (int it = 0; it < NK; ++it) {
        asm volatile("cp.async.wait_group 1;");
        __syncthreads();
        unsigned aB = tiles + (it & 1) * STAGE;
        if (warp < 8) {
            unsigned bB = aB + 16384;
            #pragma unroll
            for (int kk = 0; kk < 4; ++kk) {
                unsigned a[2][4];
                #pragma unroll
                for (int mt = 0; mt < 2; ++mt) {
                    int r = wm * 32 + mt * 16 + (sub & 1) * 8 + (lane & 7);
                    int c = kk * 2 + (sub >> 1);
                    ldm_x4(a[mt][0], a[mt][1], a[mt][2], a[mt][3],
                           aB + r * 128 + ((c ^ (r & 7)) << 4));
                }
                unsigned b[NSETS][NTP * 2][2];
                #pragma unroll
                for (int s = 0; s < NSETS; s++)
                    #pragma unroll
                    for (int ntp = 0; ntp < NTP; ntp++) {
                        int r = s * 64 + wn * (NTP * 16) + ntp * 16 + (sub >> 1) * 8 + (lane & 7);
                        int c = kk * 2 + (sub & 1);
                        unsigned q0, q1, q2, q3;
                        ldm_x4(q0, q1, q2, q3, bB + r * 128 + ((c ^ (r & 7)) << 4));
                        b[s][ntp * 2][0] = q0;     b[s][ntp * 2][1] = q1;
                        b[s][ntp * 2 + 1][0] = q2; b[s][ntp * 2 + 1][1] = q3;
                    }
                #pragma unroll
                for (int s = 0; s < NSETS; s++)
                    #pragma unroll
                    for (int mt = 0; mt < 2; mt++)
                        #pragma unroll
                        for (int nt = 0; nt < NTP * 2; nt++)
                            mma_s8(&acc[(((s * 2 + mt) * (NTP * 2)) + nt) * 4], a[mt], b[s][nt]);
            }
        } else {
            unsigned bB = aB + 32768;
            unsigned aBase = aB + ti * 128;
            unsigned bBase = bB + ci * 128;
            #pragma unroll 2
            for (int h = 0; h < 16; ++h) {
                int kb = h >> 1, half = (h & 1) << 3;
                unsigned aOff = aBase + (((kb ^ aSw) << 4) + half);
                unsigned bOff = bBase + (((kb ^ bSw) << 4) + half);
                int2 a2[8], b2[8];
                #pragma unroll
                for (int j = 0; j < 8; j++) a2[j] = lds64(aOff + j * 2048);
                #pragma unroll
                for (int l = 0; l < 8; l++) b2[l] = lds64(bOff + l * 2048);
                #pragma unroll
                for (int j = 0; j < 8; j++)
                    #pragma unroll
                    for (int l = 0; l < 8; l++)
                        acc[j * 8 + l] = __dp4a(a2[j].x, b2[l].x, acc[j * 8 + l]);
                #pragma unroll
                for (int j = 0; j < 8; j++)
                    #pragma unroll
                    for (int l = 0; l < 8; l++)
                        acc[j * 8 + l] = __dp4a(a2[j].y, b2[l].y, acc[j * 8 + l]);
            }
        }
        __syncthreads();
        if (it + 2 < NK) load(it + 2);
        asm volatile("cp.async.commit_group;");
    }

    // ---------------- epilogues (R13 verbatim) ----------------
    float sw = g_s[PHASE - 1];
    if (warp < 8) {
        #pragma unroll
        for (int mt = 0; mt < 2; ++mt) {
            #pragma unroll
            for (int rh = 0; rh < 2; ++rh) {
                int rloc = wm * 32 + mt * 16 + rh * 8 + (lane >> 2);
                int grow = mBase + rloc;
                float d = dA[grow] * sw;
                if (PHASE == 1) {
                    float rmax = 0.f;
                    #pragma unroll
                    for (int nt = 0; nt < 4; nt++) {
                        float v0 = acc[((mt * 4) + nt) * 4 + rh * 2] * d;
                        float v1 = acc[((mt * 4) + nt) * 4 + rh * 2 + 1] * d;
                        float gg0 = acc[(((2 + mt) * 4) + nt) * 4 + rh * 2] * d;
                        float gg1 = acc[(((2 + mt) * 4) + nt) * 4 + rh * 2 + 1] * d;
                        float h0 = v0 * (gg0 / (1.f + expf(-gg0)));
                        float h1 = v1 * (gg1 / (1.f + expf(-gg1)));
                        rmax = fmaxf(rmax, fmaxf(fabsf(h0), fabsf(h1)));
                        int gc = nT + wn * 32 + nt * 8 + (lane & 3) * 2;
                        *(float2*)(g_h2 + (size_t)grow * HID + gc) = make_float2(h0, h1);
                    }
                    atomicMax(&s_amax[rloc], __float_as_uint(rmax));
                } else {
                    #pragma unroll
                    for (int nt = 0; nt < 8; nt++) {
                        int gc = nT + wn * 64 + nt * 8 + (lane & 3) * 2;
                        float2 rr = *(const float2*)(resid + (size_t)grow * DM + gc);
                        float2 o = make_float2(rr.x + acc[(mt * 8 + nt) * 4 + rh * 2] * d,
                                               rr.y + acc[(mt * 8 + nt) * 4 + rh * 2 + 1] * d);
                        *(float2*)(dout + (size_t)grow * DM + gc) = o;
                    }
                }
            }
        }
    } else {
        #pragma unroll
        for (int j = 0; j < 8; j++) {
            int tok = ti + 16 * j;
            int grow = mBase + tok;
            float d = dA[grow] * sw;
            if (PHASE == 1) {
                float rmax = 0.f;
                #pragma unroll
                for (int l = 0; l < 4; l++) {
                    float v = acc[j * 8 + l] * d;
                    float g = acc[j * 8 + l + 4] * d;
                    float h = v * (g / (1.f + expf(-g)));
                    rmax = fmaxf(rmax, fabsf(h));
                    g_h2[(size_t)grow * HID + nT + 64 + ci + 16 * l] = h;
                }
                atomicMax(&s_amax[tok], __float_as_uint(rmax));
            } else {
                #pragma unroll
                for (int l = 0; l < 8; l++) {
                    int gc = nT + 128 + ci + 16 * l;
                    dout[(size_t)grow * DM + gc] =
                        resid[(size_t)grow * DM + gc] + acc[j * 8 + l] * d;
                }
            }
        }
    }
    if (PHASE == 1) {
        __syncthreads();
        for (int i = tid; i < 128; i += 512)
            atomicMax(&g_amax2[mBase + i], s_amax[i]);
    }
}

// ---------------- quantize h2 ----------------
__global__ void k_h2quant(int rowOff) {
    int row = rowOff + blockIdx.y;
    float am = fmaxf(__uint_as_float(g_amax2[row]), 1e-5f);
    float sc = 127.f / am;
    int i = blockIdx.x * 256 + threadIdx.x;
    float4 v = ((const float4*)(g_h2 + (size_t)row * HID))[i];
    char4 c;
    c.x = q8(v.x, sc); c.y = q8(v.y, sc); c.z = q8(v.z, sc); c.w = q8(v.w, sc);
    ((char4*)(g_h2q + (size_t)row * HID))[i] = c;
    if (i == 0) g_d2[row] = am * (1.f / 127.f);
}

// ---------------- launcher: w_out pipeline fully hidden on side stream ----------------
extern "C" void kernel_launch(void* const* d_in, const int* in_sizes, int n_in,
                              void* d_out, int out_size) {
    const float* x    = (const float*)d_in[0];
    const float* nw   = (const float*)d_in[1];
    const float* wgv  = (const float*)d_in[2];
    const float* wout = (const float*)d_in[3];
    float* out = (float*)d_out;

    static bool inited = false;
    static cudaStream_t sB;
    static cudaEvent_t evS, evW;
    if (!inited) {
        cudaStreamCreateWithFlags(&sB, cudaStreamNonBlocking);
        cudaEventCreateWithFlags(&evS, cudaEventDisableTiming);
        cudaEventCreateWithFlags(&evW, cudaEventDisableTiming);
        cudaFuncSetAttribute(k_fused<1>, cudaFuncAttributeMaxDynamicSharedMemorySize, SMEM_SZ);
        cudaFuncSetAttribute(k_fused<2>, cudaFuncAttributeMaxDynamicSharedMemorySize, SMEM_SZ);
        inited = true;
    }
    const cudaStream_t s0 = 0;

    k_zero<<<1, 32, 0, s0>>>();                       // origin of capture
    cudaEventRecord(evS, s0);
    cudaStreamWaitEvent(sB, evS, 0);                  // fork sB into capture

    // side stream: full w_out pipeline (hidden under rmsquant/absmean_gv/fused1)
    k_absmean<<<1024, 256, 0, sB>>>((const float4*)wout, DM * HID / 4, 1);
    k_wquant<<<2048, 256, 0, sB>>>((const float4*)wout, DM * HID / 4, 1);
    cudaEventRecord(evW, sB);

    // main stream: activation pipeline + w_gv pipeline + GEMMs
    k_rmsquant<<<TOK, 256, 0, s0>>>((const float4*)x, (const float4*)nw);
    k_absmean<<<1024, 256, 0, s0>>>((const float4*)wgv, 2 * HID * DM / 4, 0);
    k_wquant<<<4096, 256, 0, s0>>>((const float4*)wgv, 2 * HID * DM / 4, 0);
    k_fused<1><<<dim3(HID / 128, TOK / 128), 512, SMEM_SZ, s0>>>(nullptr, nullptr, 0);
    k_h2quant<<<dim3(8, TOK), 256, 0, s0>>>(0);
    cudaStreamWaitEvent(s0, evW, 0);                  // join w_out pipeline
    k_fused<2><<<dim3(DM / 256, TOK / 128), 512, SMEM_SZ, s0>>>(x, out, 0);
}